// round 3
// baseline (speedup 1.0000x reference)
#include <cuda_runtime.h>
#include <math.h>

#define INC 128
#define HID 64
#define MAXN 100000

// Scratch (device globals — no allocation allowed)
__device__ int   g_deg [MAXN];
__device__ float g_dinv[MAXN];
__device__ float g_feat1[(size_t)MAXN * HID];
__device__ float g_agg1 [(size_t)MAXN * HID];
__device__ float g_feat2[(size_t)MAXN * HID];
__device__ float g_agg2 [(size_t)MAXN * HID];

__global__ void k_zero_deg(int n) {
    int i = blockIdx.x * blockDim.x + threadIdx.x;
    if (i < n) g_deg[i] = 0;
}

__global__ void k_deg(const int* __restrict__ ei, int E) {
    int e = blockIdx.x * blockDim.x + threadIdx.x;
    if (e < E) atomicAdd(&g_deg[ei[(size_t)E + e]], 1);
}

__global__ void k_dinv(int n) {
    int i = blockIdx.x * blockDim.x + threadIdx.x;
    if (i < n) g_dinv[i] = rsqrtf((float)(g_deg[i] + 1));   // +1 self-loop
}

// GEMM1: g_feat1 = dinv ⊙ (x @ W1);  g_agg1 = g_feat1 (self-loop init)
// Tile: 128 rows x 64 cols, 256 threads, microtile 8x4, K-chunks of 32.
__global__ __launch_bounds__(256) void k_gemm1(const float* __restrict__ x,
                                               const float* __restrict__ W,
                                               int N) {
    __shared__ float As[128][33];
    __shared__ float Bs[32][64];
    int t = threadIdx.x;
    int row0 = blockIdx.x * 128;
    int rr = (t >> 4) * 8;
    int cc = (t & 15) * 4;
    float acc[8][4];
#pragma unroll
    for (int i = 0; i < 8; i++)
#pragma unroll
        for (int j = 0; j < 4; j++) acc[i][j] = 0.f;

    for (int kc = 0; kc < INC; kc += 32) {
#pragma unroll
        for (int j = 0; j < 4; j++) {
            int id = t + 256 * j;
            int r = id >> 3, k4 = id & 7;
            int grow = row0 + r;
            float4 v = make_float4(0.f, 0.f, 0.f, 0.f);
            if (grow < N) v = *(const float4*)(x + (size_t)grow * INC + kc + k4 * 4);
            As[r][k4 * 4 + 0] = v.x; As[r][k4 * 4 + 1] = v.y;
            As[r][k4 * 4 + 2] = v.z; As[r][k4 * 4 + 3] = v.w;
        }
#pragma unroll
        for (int j = 0; j < 2; j++) {
            int id = t + 256 * j;
            int k = id >> 4, c4 = id & 15;
            *(float4*)(&Bs[k][c4 * 4]) = *(const float4*)(W + (size_t)(kc + k) * HID + c4 * 4);
        }
        __syncthreads();
#pragma unroll
        for (int k = 0; k < 32; k++) {
            float4 bv = *(const float4*)(&Bs[k][cc]);
            float a[8];
#pragma unroll
            for (int i = 0; i < 8; i++) a[i] = As[rr + i][k];
#pragma unroll
            for (int i = 0; i < 8; i++) {
                acc[i][0] += a[i] * bv.x; acc[i][1] += a[i] * bv.y;
                acc[i][2] += a[i] * bv.z; acc[i][3] += a[i] * bv.w;
            }
        }
        __syncthreads();
    }
#pragma unroll
    for (int i = 0; i < 8; i++) {
        int grow = row0 + rr + i;
        if (grow < N) {
            float s = g_dinv[grow];
            float4 o = make_float4(acc[i][0] * s, acc[i][1] * s, acc[i][2] * s, acc[i][3] * s);
            *(float4*)(g_feat1 + (size_t)grow * HID + cc) = o;
            *(float4*)(g_agg1  + (size_t)grow * HID + cc) = o;
        }
    }
}

// Scatter: agg[dst] += feat[src] over all edges. 16 threads per edge,
// float4 gather + 4 scalar atomicAdd (compiles to RED.ADD.F32).
__global__ void k_scatter(const int* __restrict__ ei, int E, int layer2) {
    long long idx = (long long)blockIdx.x * blockDim.x + threadIdx.x;
    long long e = idx >> 4;
    if (e >= E) return;
    int l = (int)idx & 15;
    const float* __restrict__ feat = layer2 ? g_feat2 : g_feat1;
    float* __restrict__ agg        = layer2 ? g_agg2  : g_agg1;
    int s = ei[e];
    int d = ei[(size_t)E + e];
    float4 v = *(const float4*)(feat + (size_t)s * HID + l * 4);
    float* p = agg + (size_t)d * HID + l * 4;
    atomicAdd(p + 0, v.x);
    atomicAdd(p + 1, v.y);
    atomicAdd(p + 2, v.z);
    atomicAdd(p + 3, v.w);
}

// GEMM2: h1 = relu(dinv ⊙ agg1 + b1);  g_feat2 = dinv ⊙ (h1 @ W2);  g_agg2 = g_feat2
__global__ __launch_bounds__(256) void k_gemm2(const float* __restrict__ W,
                                               const float* __restrict__ b1,
                                               int N) {
    __shared__ float As[128][33];
    __shared__ float Bs[32][64];
    int t = threadIdx.x;
    int row0 = blockIdx.x * 128;
    int rr = (t >> 4) * 8;
    int cc = (t & 15) * 4;
    float acc[8][4];
#pragma unroll
    for (int i = 0; i < 8; i++)
#pragma unroll
        for (int j = 0; j < 4; j++) acc[i][j] = 0.f;

    for (int kc = 0; kc < HID; kc += 32) {
#pragma unroll
        for (int j = 0; j < 4; j++) {
            int id = t + 256 * j;
            int r = id >> 3, k4 = id & 7;
            int grow = row0 + r;
            float av0 = 0.f, av1 = 0.f, av2 = 0.f, av3 = 0.f;
            if (grow < N) {
                float4 v = *(const float4*)(g_agg1 + (size_t)grow * HID + kc + k4 * 4);
                float dv = g_dinv[grow];
                av0 = fmaxf(fmaf(v.x, dv, __ldg(b1 + kc + k4 * 4 + 0)), 0.f);
                av1 = fmaxf(fmaf(v.y, dv, __ldg(b1 + kc + k4 * 4 + 1)), 0.f);
                av2 = fmaxf(fmaf(v.z, dv, __ldg(b1 + kc + k4 * 4 + 2)), 0.f);
                av3 = fmaxf(fmaf(v.w, dv, __ldg(b1 + kc + k4 * 4 + 3)), 0.f);
            }
            As[r][k4 * 4 + 0] = av0; As[r][k4 * 4 + 1] = av1;
            As[r][k4 * 4 + 2] = av2; As[r][k4 * 4 + 3] = av3;
        }
#pragma unroll
        for (int j = 0; j < 2; j++) {
            int id = t + 256 * j;
            int k = id >> 4, c4 = id & 15;
            *(float4*)(&Bs[k][c4 * 4]) = *(const float4*)(W + (size_t)(kc + k) * HID + c4 * 4);
        }
        __syncthreads();
#pragma unroll
        for (int k = 0; k < 32; k++) {
            float4 bv = *(const float4*)(&Bs[k][cc]);
            float a[8];
#pragma unroll
            for (int i = 0; i < 8; i++) a[i] = As[rr + i][k];
#pragma unroll
            for (int i = 0; i < 8; i++) {
                acc[i][0] += a[i] * bv.x; acc[i][1] += a[i] * bv.y;
                acc[i][2] += a[i] * bv.z; acc[i][3] += a[i] * bv.w;
            }
        }
        __syncthreads();
    }
#pragma unroll
    for (int i = 0; i < 8; i++) {
        int grow = row0 + rr + i;
        if (grow < N) {
            float s = g_dinv[grow];
            float4 o = make_float4(acc[i][0] * s, acc[i][1] * s, acc[i][2] * s, acc[i][3] * s);
            *(float4*)(g_feat2 + (size_t)grow * HID + cc) = o;
            *(float4*)(g_agg2  + (size_t)grow * HID + cc) = o;
        }
    }
}

// Output: logits[v] = relu(dinv[v]*agg2[v] + b2) . Wc + bc   (warp per node)
__global__ void k_out(const float* __restrict__ b2, const float* __restrict__ Wc,
                      const float* __restrict__ bc, float* __restrict__ out, int N) {
    long long idx = (long long)blockIdx.x * blockDim.x + threadIdx.x;
    int v = (int)(idx >> 5);
    if (v >= N) return;
    int lane = (int)idx & 31;
    float dv = g_dinv[v];
    float a0 = g_agg2[(size_t)v * HID + lane];
    float a1 = g_agg2[(size_t)v * HID + 32 + lane];
    float h0 = fmaxf(fmaf(a0, dv, __ldg(b2 + lane)), 0.f);
    float h1 = fmaxf(fmaf(a1, dv, __ldg(b2 + 32 + lane)), 0.f);
    float p = h0 * __ldg(Wc + lane) + h1 * __ldg(Wc + 32 + lane);
#pragma unroll
    for (int o = 16; o > 0; o >>= 1) p += __shfl_down_sync(0xffffffffu, p, o);
    if (lane == 0) out[v] = p + __ldg(bc);
}

extern "C" void kernel_launch(void* const* d_in, const int* in_sizes, int n_in,
                              void* d_out, int out_size) {
    const float* x  = (const float*)d_in[0];
    const int*   ei = (const int*)d_in[1];
    const float* W1 = (const float*)d_in[2];
    const float* b1 = (const float*)d_in[3];
    const float* W2 = (const float*)d_in[4];
    const float* b2 = (const float*)d_in[5];
    const float* Wc = (const float*)d_in[6];
    const float* bc = (const float*)d_in[7];
    float* out = (float*)d_out;

    int N = in_sizes[0] / INC;
    int E = in_sizes[1] / 2;

    k_zero_deg<<<(N + 255) / 256, 256>>>(N);
    k_deg<<<(E + 255) / 256, 256>>>(ei, E);
    k_dinv<<<(N + 255) / 256, 256>>>(N);

    k_gemm1<<<(N + 127) / 128, 256>>>(x, W1, N);
    {
        long long tot = (long long)E * 16;
        k_scatter<<<(unsigned)((tot + 255) / 256), 256>>>(ei, E, 0);
    }
    k_gemm2<<<(N + 127) / 128, 256>>>(W2, b1, N);
    {
        long long tot = (long long)E * 16;
        k_scatter<<<(unsigned)((tot + 255) / 256), 256>>>(ei, E, 1);
    }
    k_out<<<(unsigned)(((long long)N * 32 + 255) / 256), 256>>>(b2, Wc, bc, out, N);
}

// round 5
// speedup vs baseline: 2.5292x; 2.5292x over previous
#include <cuda_runtime.h>
#include <math.h>

#define INC 128
#define HID 64
#define MAXN 100000
#define MAXE 1600000
#define SCAN_B 256

// Scratch (device globals — no allocation allowed)
__device__ int   g_deg [MAXN];
__device__ int   g_incl[MAXN];
__device__ int   g_bsum[512];
__device__ int   g_boff[512];
__device__ int   g_rowptr[MAXN + 1];
__device__ int   g_cur [MAXN];
__device__ int   g_csrc[MAXE];
__device__ float g_dinv[MAXN];
__device__ float g_feat1[(size_t)MAXN * HID];
__device__ float g_agg1 [(size_t)MAXN * HID];
__device__ float g_feat2[(size_t)MAXN * HID];
__device__ float g_agg2 [(size_t)MAXN * HID];

__global__ void k_zero_deg(int n) {
    int i = blockIdx.x * blockDim.x + threadIdx.x;
    if (i < n) g_deg[i] = 0;
}

__global__ void k_deg(const int* __restrict__ ei, int E) {
    int e = blockIdx.x * blockDim.x + threadIdx.x;
    if (e < E) atomicAdd(&g_deg[ei[(size_t)E + e]], 1);
}

// Pass 1: per-block inclusive scan of deg, block sums out
__global__ void k_scan1(int n) {
    __shared__ int s[SCAN_B];
    int i = blockIdx.x * SCAN_B + threadIdx.x;
    int v = (i < n) ? g_deg[i] : 0;
    s[threadIdx.x] = v;
    __syncthreads();
#pragma unroll
    for (int o = 1; o < SCAN_B; o <<= 1) {
        int t = 0;
        if (threadIdx.x >= o) t = s[threadIdx.x - o];
        __syncthreads();
        s[threadIdx.x] += t;
        __syncthreads();
    }
    if (i < n) g_incl[i] = s[threadIdx.x];
    if (threadIdx.x == SCAN_B - 1) g_bsum[blockIdx.x] = s[SCAN_B - 1];
}

// Pass 2: exclusive scan of block sums (single block, nb <= 512)
__global__ void k_scan2(int nb) {
    __shared__ int s[512];
    int t = threadIdx.x;
    int v = (t < nb) ? g_bsum[t] : 0;
    s[t] = v;
    __syncthreads();
#pragma unroll
    for (int o = 1; o < 512; o <<= 1) {
        int u = 0;
        if (t >= o) u = s[t - o];
        __syncthreads();
        s[t] += u;
        __syncthreads();
    }
    if (t < nb) g_boff[t] = s[t] - v;   // exclusive prefix
}

// Pass 3: rowptr, cursors, dinv
__global__ void k_finalize(int n) {
    int i = blockIdx.x * blockDim.x + threadIdx.x;
    if (i >= n) return;
    int incl = g_incl[i] + g_boff[i / SCAN_B];
    g_rowptr[i + 1] = incl;
    g_cur[i] = incl - g_deg[i];
    if (i == 0) g_rowptr[0] = 0;
    g_dinv[i] = rsqrtf((float)(g_deg[i] + 1));   // +1 self-loop
}

// Fill CSR: csrc grouped by dst
__global__ void k_fill(const int* __restrict__ ei, int E) {
    int e = blockIdx.x * blockDim.x + threadIdx.x;
    if (e >= E) return;
    int d = ei[(size_t)E + e];
    int pos = atomicAdd(&g_cur[d], 1);
    g_csrc[pos] = ei[e];
}

// GEMM1: g_feat1 = dinv ⊙ (x @ W1)
__global__ __launch_bounds__(256) void k_gemm1(const float* __restrict__ x,
                                               const float* __restrict__ W,
                                               int N) {
    __shared__ float As[128][33];
    __shared__ float Bs[32][64];
    int t = threadIdx.x;
    int row0 = blockIdx.x * 128;
    int rr = (t >> 4) * 8;
    int cc = (t & 15) * 4;
    float acc[8][4];
#pragma unroll
    for (int i = 0; i < 8; i++)
#pragma unroll
        for (int j = 0; j < 4; j++) acc[i][j] = 0.f;

    for (int kc = 0; kc < INC; kc += 32) {
#pragma unroll
        for (int j = 0; j < 4; j++) {
            int id = t + 256 * j;
            int r = id >> 3, k4 = id & 7;
            int grow = row0 + r;
            float4 v = make_float4(0.f, 0.f, 0.f, 0.f);
            if (grow < N) v = *(const float4*)(x + (size_t)grow * INC + kc + k4 * 4);
            As[r][k4 * 4 + 0] = v.x; As[r][k4 * 4 + 1] = v.y;
            As[r][k4 * 4 + 2] = v.z; As[r][k4 * 4 + 3] = v.w;
        }
#pragma unroll
        for (int j = 0; j < 2; j++) {
            int id = t + 256 * j;
            int k = id >> 4, c4 = id & 15;
            *(float4*)(&Bs[k][c4 * 4]) = *(const float4*)(W + (size_t)(kc + k) * HID + c4 * 4);
        }
        __syncthreads();
#pragma unroll
        for (int k = 0; k < 32; k++) {
            float4 bv = *(const float4*)(&Bs[k][cc]);
            float a[8];
#pragma unroll
            for (int i = 0; i < 8; i++) a[i] = As[rr + i][k];
#pragma unroll
            for (int i = 0; i < 8; i++) {
                acc[i][0] += a[i] * bv.x; acc[i][1] += a[i] * bv.y;
                acc[i][2] += a[i] * bv.z; acc[i][3] += a[i] * bv.w;
            }
        }
        __syncthreads();
    }
#pragma unroll
    for (int i = 0; i < 8; i++) {
        int grow = row0 + rr + i;
        if (grow < N) {
            float s = g_dinv[grow];
            float4 o = make_float4(acc[i][0] * s, acc[i][1] * s, acc[i][2] * s, acc[i][3] * s);
            *(float4*)(g_feat1 + (size_t)grow * HID + cc) = o;
        }
    }
}

// Aggregate: agg[v] = feat[v] + sum_{src in CSR row v} feat[src]
// One warp per node; lane owns 2 columns (float2); src indices broadcast via shfl.
// Buffers selected in device code (device-symbol addresses are invalid on host!).
__global__ __launch_bounds__(256) void k_aggregate(int N, int layer2) {
    const float* __restrict__ feat = layer2 ? g_feat2 : g_feat1;
    float* __restrict__ agg        = layer2 ? g_agg2  : g_agg1;
    int gtid = blockIdx.x * blockDim.x + threadIdx.x;
    int v = gtid >> 5;
    if (v >= N) return;
    int lane = threadIdx.x & 31;
    int beg = g_rowptr[v];
    int end = g_rowptr[v + 1];

    float2 acc = *(const float2*)(feat + (size_t)v * HID + lane * 2);   // self-loop

    for (int b = beg; b < end; b += 32) {
        int n = end - b;
        if (n > 32) n = 32;
        int s = (lane < n) ? g_csrc[b + lane] : 0;
#pragma unroll 4
        for (int j = 0; j < n; j++) {
            int sj = __shfl_sync(0xffffffffu, s, j);
            float2 w = *(const float2*)(feat + (size_t)sj * HID + lane * 2);
            acc.x += w.x;
            acc.y += w.y;
        }
    }
    *(float2*)(agg + (size_t)v * HID + lane * 2) = acc;
}

// GEMM2: h1 = relu(dinv ⊙ agg1 + b1);  g_feat2 = dinv ⊙ (h1 @ W2)
__global__ __launch_bounds__(256) void k_gemm2(const float* __restrict__ W,
                                               const float* __restrict__ b1,
                                               int N) {
    __shared__ float As[128][33];
    __shared__ float Bs[32][64];
    int t = threadIdx.x;
    int row0 = blockIdx.x * 128;
    int rr = (t >> 4) * 8;
    int cc = (t & 15) * 4;
    float acc[8][4];
#pragma unroll
    for (int i = 0; i < 8; i++)
#pragma unroll
        for (int j = 0; j < 4; j++) acc[i][j] = 0.f;

    for (int kc = 0; kc < HID; kc += 32) {
#pragma unroll
        for (int j = 0; j < 4; j++) {
            int id = t + 256 * j;
            int r = id >> 3, k4 = id & 7;
            int grow = row0 + r;
            float av0 = 0.f, av1 = 0.f, av2 = 0.f, av3 = 0.f;
            if (grow < N) {
                float4 v = *(const float4*)(g_agg1 + (size_t)grow * HID + kc + k4 * 4);
                float dv = g_dinv[grow];
                av0 = fmaxf(fmaf(v.x, dv, __ldg(b1 + kc + k4 * 4 + 0)), 0.f);
                av1 = fmaxf(fmaf(v.y, dv, __ldg(b1 + kc + k4 * 4 + 1)), 0.f);
                av2 = fmaxf(fmaf(v.z, dv, __ldg(b1 + kc + k4 * 4 + 2)), 0.f);
                av3 = fmaxf(fmaf(v.w, dv, __ldg(b1 + kc + k4 * 4 + 3)), 0.f);
            }
            As[r][k4 * 4 + 0] = av0; As[r][k4 * 4 + 1] = av1;
            As[r][k4 * 4 + 2] = av2; As[r][k4 * 4 + 3] = av3;
        }
#pragma unroll
        for (int j = 0; j < 2; j++) {
            int id = t + 256 * j;
            int k = id >> 4, c4 = id & 15;
            *(float4*)(&Bs[k][c4 * 4]) = *(const float4*)(W + (size_t)(kc + k) * HID + c4 * 4);
        }
        __syncthreads();
#pragma unroll
        for (int k = 0; k < 32; k++) {
            float4 bv = *(const float4*)(&Bs[k][cc]);
            float a[8];
#pragma unroll
            for (int i = 0; i < 8; i++) a[i] = As[rr + i][k];
#pragma unroll
            for (int i = 0; i < 8; i++) {
                acc[i][0] += a[i] * bv.x; acc[i][1] += a[i] * bv.y;
                acc[i][2] += a[i] * bv.z; acc[i][3] += a[i] * bv.w;
            }
        }
        __syncthreads();
    }
#pragma unroll
    for (int i = 0; i < 8; i++) {
        int grow = row0 + rr + i;
        if (grow < N) {
            float s = g_dinv[grow];
            float4 o = make_float4(acc[i][0] * s, acc[i][1] * s, acc[i][2] * s, acc[i][3] * s);
            *(float4*)(g_feat2 + (size_t)grow * HID + cc) = o;
        }
    }
}

// Output: logits[v] = relu(dinv[v]*agg2[v] + b2) . Wc + bc   (warp per node)
__global__ void k_out(const float* __restrict__ b2, const float* __restrict__ Wc,
                      const float* __restrict__ bc, float* __restrict__ out, int N) {
    long long idx = (long long)blockIdx.x * blockDim.x + threadIdx.x;
    int v = (int)(idx >> 5);
    if (v >= N) return;
    int lane = (int)idx & 31;
    float dv = g_dinv[v];
    float a0 = g_agg2[(size_t)v * HID + lane];
    float a1 = g_agg2[(size_t)v * HID + 32 + lane];
    float h0 = fmaxf(fmaf(a0, dv, __ldg(b2 + lane)), 0.f);
    float h1 = fmaxf(fmaf(a1, dv, __ldg(b2 + 32 + lane)), 0.f);
    float p = h0 * __ldg(Wc + lane) + h1 * __ldg(Wc + 32 + lane);
#pragma unroll
    for (int o = 16; o > 0; o >>= 1) p += __shfl_down_sync(0xffffffffu, p, o);
    if (lane == 0) out[v] = p + __ldg(bc);
}

extern "C" void kernel_launch(void* const* d_in, const int* in_sizes, int n_in,
                              void* d_out, int out_size) {
    const float* x  = (const float*)d_in[0];
    const int*   ei = (const int*)d_in[1];
    const float* W1 = (const float*)d_in[2];
    const float* b1 = (const float*)d_in[3];
    const float* W2 = (const float*)d_in[4];
    const float* b2 = (const float*)d_in[5];
    const float* Wc = (const float*)d_in[6];
    const float* bc = (const float*)d_in[7];
    float* out = (float*)d_out;

    int N = in_sizes[0] / INC;
    int E = in_sizes[1] / 2;
    int nb = (N + SCAN_B - 1) / SCAN_B;

    // CSR build + dinv
    k_zero_deg<<<(N + 255) / 256, 256>>>(N);
    k_deg<<<(E + 255) / 256, 256>>>(ei, E);
    k_scan1<<<nb, SCAN_B>>>(N);
    k_scan2<<<1, 512>>>(nb);
    k_finalize<<<(N + 255) / 256, 256>>>(N);
    k_fill<<<(E + 255) / 256, 256>>>(ei, E);

    // Layer 1
    k_gemm1<<<(N + 127) / 128, 256>>>(x, W1, N);
    k_aggregate<<<(N * 32 + 255) / 256, 256>>>(N, 0);

    // Layer 2
    k_gemm2<<<(N + 127) / 128, 256>>>(W2, b1, N);
    k_aggregate<<<(N * 32 + 255) / 256, 256>>>(N, 1);

    // Classifier
    k_out<<<(unsigned)(((long long)N * 32 + 255) / 256), 256>>>(b2, Wc, bc, out, N);
}

// round 6
// speedup vs baseline: 2.6941x; 1.0652x over previous
#include <cuda_runtime.h>
#include <math.h>

#define INC 128
#define HID 64
#define MAXN 100000
#define MAXE 1600000
#define SCAN_B 256

__device__ int   g_deg [MAXN];
__device__ int   g_incl[MAXN];
__device__ int   g_bsum[512];
__device__ int   g_boff[512];
__device__ int   g_rowptr[MAXN + 1];
__device__ int   g_cur [MAXN];
__device__ int   g_csrc[MAXE];
__device__ float g_dinv[MAXN];
__device__ float g_feat1[(size_t)MAXN * HID];
__device__ float g_agg1 [(size_t)MAXN * HID];
__device__ float g_feat2[(size_t)MAXN * HID];

__global__ void k_zero_deg(int n) {
    int i = blockIdx.x * blockDim.x + threadIdx.x;
    if (i < n) g_deg[i] = 0;
}

__global__ void k_deg(const int* __restrict__ ei, int E) {
    int e = blockIdx.x * blockDim.x + threadIdx.x;
    if (e < E) atomicAdd(&g_deg[ei[(size_t)E + e]], 1);
}

// Pass 1: per-block inclusive scan of deg (+ dinv, which only needs deg)
__global__ void k_scan1(int n) {
    __shared__ int s[SCAN_B];
    int i = blockIdx.x * SCAN_B + threadIdx.x;
    int v = (i < n) ? g_deg[i] : 0;
    if (i < n) g_dinv[i] = rsqrtf((float)(v + 1));   // +1 self-loop
    s[threadIdx.x] = v;
    __syncthreads();
#pragma unroll
    for (int o = 1; o < SCAN_B; o <<= 1) {
        int t = 0;
        if (threadIdx.x >= o) t = s[threadIdx.x - o];
        __syncthreads();
        s[threadIdx.x] += t;
        __syncthreads();
    }
    if (i < n) g_incl[i] = s[threadIdx.x];
    if (threadIdx.x == SCAN_B - 1) g_bsum[blockIdx.x] = s[SCAN_B - 1];
}

// Pass 2: exclusive scan of block sums (single block, nb <= 512)
__global__ void k_scan2(int nb) {
    __shared__ int s[512];
    int t = threadIdx.x;
    int v = (t < nb) ? g_bsum[t] : 0;
    s[t] = v;
    __syncthreads();
#pragma unroll
    for (int o = 1; o < 512; o <<= 1) {
        int u = 0;
        if (t >= o) u = s[t - o];
        __syncthreads();
        s[t] += u;
        __syncthreads();
    }
    if (t < nb) g_boff[t] = s[t] - v;
}

// Pass 3: rowptr + cursors
__global__ void k_finalize(int n) {
    int i = blockIdx.x * blockDim.x + threadIdx.x;
    if (i >= n) return;
    int incl = g_incl[i] + g_boff[i / SCAN_B];
    g_rowptr[i + 1] = incl;
    g_cur[i] = incl - g_deg[i];
    if (i == 0) g_rowptr[0] = 0;
}

__global__ void k_fill(const int* __restrict__ ei, int E) {
    int e = blockIdx.x * blockDim.x + threadIdx.x;
    if (e >= E) return;
    int d = ei[(size_t)E + e];
    int pos = atomicAdd(&g_cur[d], 1);
    g_csrc[pos] = ei[e];
}

// GEMM1: g_feat1 = dinv ⊙ (x @ W1). Double-buffered smem pipeline.
__global__ __launch_bounds__(256) void k_gemm1(const float* __restrict__ x,
                                               const float* __restrict__ W,
                                               int N) {
    __shared__ float As[2][128][33];
    __shared__ float Bs[2][32][64];
    int t = threadIdx.x;
    int row0 = blockIdx.x * 128;
    int rr = (t >> 4) * 8;
    int cc = (t & 15) * 4;
    float acc[8][4];
#pragma unroll
    for (int i = 0; i < 8; i++)
#pragma unroll
        for (int j = 0; j < 4; j++) acc[i][j] = 0.f;

    float4 pa[4], pb[2];
    const int ra  = (t * 4) >> 3 >> 2;        // unused placeholder removed below
    (void)ra;

#define LDG_CHUNK(kc)                                                          \
    {                                                                          \
        _Pragma("unroll")                                                      \
        for (int j = 0; j < 4; j++) {                                          \
            int id = t + 256 * j;                                              \
            int r = id >> 3, k4 = id & 7;                                      \
            int grow = row0 + r;                                               \
            pa[j] = make_float4(0.f, 0.f, 0.f, 0.f);                           \
            if (grow < N)                                                      \
                pa[j] = *(const float4*)(x + (size_t)grow * INC + (kc) + k4 * 4); \
        }                                                                      \
        _Pragma("unroll")                                                      \
        for (int j = 0; j < 2; j++) {                                          \
            int id = t + 256 * j;                                              \
            int k = id >> 4, c4 = id & 15;                                     \
            pb[j] = *(const float4*)(W + (size_t)((kc) + k) * HID + c4 * 4);   \
        }                                                                      \
    }

#define STS_CHUNK(buf)                                                         \
    {                                                                          \
        _Pragma("unroll")                                                      \
        for (int j = 0; j < 4; j++) {                                          \
            int id = t + 256 * j;                                              \
            int r = id >> 3, k4 = id & 7;                                      \
            As[buf][r][k4 * 4 + 0] = pa[j].x; As[buf][r][k4 * 4 + 1] = pa[j].y; \
            As[buf][r][k4 * 4 + 2] = pa[j].z; As[buf][r][k4 * 4 + 3] = pa[j].w; \
        }                                                                      \
        _Pragma("unroll")                                                      \
        for (int j = 0; j < 2; j++) {                                          \
            int id = t + 256 * j;                                              \
            int k = id >> 4, c4 = id & 15;                                     \
            *(float4*)(&Bs[buf][k][c4 * 4]) = pb[j];                           \
        }                                                                      \
    }

    LDG_CHUNK(0);
    STS_CHUNK(0);
    __syncthreads();

#pragma unroll
    for (int kc = 0; kc < 4; kc++) {
        int cur = kc & 1;
        if (kc < 3) LDG_CHUNK((kc + 1) * 32);
#pragma unroll
        for (int k = 0; k < 32; k++) {
            float4 bv = *(const float4*)(&Bs[cur][k][cc]);
            float a[8];
#pragma unroll
            for (int i = 0; i < 8; i++) a[i] = As[cur][rr + i][k];
#pragma unroll
            for (int i = 0; i < 8; i++) {
                acc[i][0] += a[i] * bv.x; acc[i][1] += a[i] * bv.y;
                acc[i][2] += a[i] * bv.z; acc[i][3] += a[i] * bv.w;
            }
        }
        if (kc < 3) STS_CHUNK(cur ^ 1);
        __syncthreads();
    }
#undef LDG_CHUNK
#undef STS_CHUNK

#pragma unroll
    for (int i = 0; i < 8; i++) {
        int grow = row0 + rr + i;
        if (grow < N) {
            float s = g_dinv[grow];
            float4 o = make_float4(acc[i][0] * s, acc[i][1] * s, acc[i][2] * s, acc[i][3] * s);
            *(float4*)(g_feat1 + (size_t)grow * HID + cc) = o;
        }
    }
}

// Layer-1 aggregate: g_agg1[v] = feat1[v] + sum_{src} feat1[src]
__global__ __launch_bounds__(256) void k_aggregate1(int N) {
    int gtid = blockIdx.x * blockDim.x + threadIdx.x;
    int v = gtid >> 5;
    if (v >= N) return;
    int lane = threadIdx.x & 31;
    int beg = g_rowptr[v];
    int end = g_rowptr[v + 1];

    float2 acc = *(const float2*)(g_feat1 + (size_t)v * HID + lane * 2);

    for (int b = beg; b < end; b += 32) {
        int n = end - b;
        if (n > 32) n = 32;
        int s = (lane < n) ? g_csrc[b + lane] : 0;
#pragma unroll 4
        for (int j = 0; j < n; j++) {
            int sj = __shfl_sync(0xffffffffu, s, j);
            float2 w = *(const float2*)(g_feat1 + (size_t)sj * HID + lane * 2);
            acc.x += w.x;
            acc.y += w.y;
        }
    }
    *(float2*)(g_agg1 + (size_t)v * HID + lane * 2) = acc;
}

// GEMM2: h1 = relu(dinv ⊙ agg1 + b1);  g_feat2 = dinv ⊙ (h1 @ W2). Double-buffered.
__global__ __launch_bounds__(256) void k_gemm2(const float* __restrict__ W,
                                               const float* __restrict__ b1,
                                               int N) {
    __shared__ float As[2][128][33];
    __shared__ float Bs[2][32][64];
    int t = threadIdx.x;
    int row0 = blockIdx.x * 128;
    int rr = (t >> 4) * 8;
    int cc = (t & 15) * 4;
    float acc[8][4];
#pragma unroll
    for (int i = 0; i < 8; i++)
#pragma unroll
        for (int j = 0; j < 4; j++) acc[i][j] = 0.f;

    float4 pa[4], pb[2];

#define LDG_CHUNK2(kc)                                                          \
    {                                                                           \
        _Pragma("unroll")                                                       \
        for (int j = 0; j < 4; j++) {                                           \
            int id = t + 256 * j;                                               \
            int r = id >> 3, k4 = id & 7;                                       \
            int grow = row0 + r;                                                \
            pa[j] = make_float4(0.f, 0.f, 0.f, 0.f);                            \
            if (grow < N) {                                                     \
                float4 v = *(const float4*)(g_agg1 + (size_t)grow * HID + (kc) + k4 * 4); \
                float dv = g_dinv[grow];                                        \
                pa[j].x = fmaxf(fmaf(v.x, dv, __ldg(b1 + (kc) + k4 * 4 + 0)), 0.f); \
                pa[j].y = fmaxf(fmaf(v.y, dv, __ldg(b1 + (kc) + k4 * 4 + 1)), 0.f); \
                pa[j].z = fmaxf(fmaf(v.z, dv, __ldg(b1 + (kc) + k4 * 4 + 2)), 0.f); \
                pa[j].w = fmaxf(fmaf(v.w, dv, __ldg(b1 + (kc) + k4 * 4 + 3)), 0.f); \
            }                                                                   \
        }                                                                       \
        _Pragma("unroll")                                                       \
        for (int j = 0; j < 2; j++) {                                           \
            int id = t + 256 * j;                                               \
            int k = id >> 4, c4 = id & 15;                                      \
            pb[j] = *(const float4*)(W + (size_t)((kc) + k) * HID + c4 * 4);    \
        }                                                                       \
    }

#define STS_CHUNK2(buf)                                                         \
    {                                                                           \
        _Pragma("unroll")                                                       \
        for (int j = 0; j < 4; j++) {                                           \
            int id = t + 256 * j;                                               \
            int r = id >> 3, k4 = id & 7;                                       \
            As[buf][r][k4 * 4 + 0] = pa[j].x; As[buf][r][k4 * 4 + 1] = pa[j].y; \
            As[buf][r][k4 * 4 + 2] = pa[j].z; As[buf][r][k4 * 4 + 3] = pa[j].w; \
        }                                                                       \
        _Pragma("unroll")                                                       \
        for (int j = 0; j < 2; j++) {                                           \
            int id = t + 256 * j;                                               \
            int k = id >> 4, c4 = id & 15;                                      \
            *(float4*)(&Bs[buf][k][c4 * 4]) = pb[j];                            \
        }                                                                       \
    }

    LDG_CHUNK2(0);
    STS_CHUNK2(0);
    __syncthreads();

#pragma unroll
    for (int kc = 0; kc < 2; kc++) {
        int cur = kc & 1;
        if (kc < 1) LDG_CHUNK2(32);
#pragma unroll
        for (int k = 0; k < 32; k++) {
            float4 bv = *(const float4*)(&Bs[cur][k][cc]);
            float a[8];
#pragma unroll
            for (int i = 0; i < 8; i++) a[i] = As[cur][rr + i][k];
#pragma unroll
            for (int i = 0; i < 8; i++) {
                acc[i][0] += a[i] * bv.x; acc[i][1] += a[i] * bv.y;
                acc[i][2] += a[i] * bv.z; acc[i][3] += a[i] * bv.w;
            }
        }
        if (kc < 1) STS_CHUNK2(cur ^ 1);
        __syncthreads();
    }
#undef LDG_CHUNK2
#undef STS_CHUNK2

#pragma unroll
    for (int i = 0; i < 8; i++) {
        int grow = row0 + rr + i;
        if (grow < N) {
            float s = g_dinv[grow];
            float4 o = make_float4(acc[i][0] * s, acc[i][1] * s, acc[i][2] * s, acc[i][3] * s);
            *(float4*)(g_feat2 + (size_t)grow * HID + cc) = o;
        }
    }
}

// Layer-2 aggregate FUSED with classifier:
// acc = feat2[v] + sum feat2[src];  h = relu(dinv*acc + b2);  out[v] = h.Wc + bc
__global__ __launch_bounds__(256) void k_agg_out(const float* __restrict__ b2,
                                                 const float* __restrict__ Wc,
                                                 const float* __restrict__ bc,
                                                 float* __restrict__ out, int N) {
    int gtid = blockIdx.x * blockDim.x + threadIdx.x;
    int v = gtid >> 5;
    if (v >= N) return;
    int lane = threadIdx.x & 31;
    int beg = g_rowptr[v];
    int end = g_rowptr[v + 1];

    float2 acc = *(const float2*)(g_feat2 + (size_t)v * HID + lane * 2);

    for (int b = beg; b < end; b += 32) {
        int n = end - b;
        if (n > 32) n = 32;
        int s = (lane < n) ? g_csrc[b + lane] : 0;
#pragma unroll 4
        for (int j = 0; j < n; j++) {
            int sj = __shfl_sync(0xffffffffu, s, j);
            float2 w = *(const float2*)(g_feat2 + (size_t)sj * HID + lane * 2);
            acc.x += w.x;
            acc.y += w.y;
        }
    }
    float dv = g_dinv[v];
    float h0 = fmaxf(fmaf(acc.x, dv, __ldg(b2 + lane * 2 + 0)), 0.f);
    float h1 = fmaxf(fmaf(acc.y, dv, __ldg(b2 + lane * 2 + 1)), 0.f);
    float p = h0 * __ldg(Wc + lane * 2) + h1 * __ldg(Wc + lane * 2 + 1);
#pragma unroll
    for (int o = 16; o > 0; o >>= 1) p += __shfl_down_sync(0xffffffffu, p, o);
    if (lane == 0) out[v] = p + __ldg(bc);
}

extern "C" void kernel_launch(void* const* d_in, const int* in_sizes, int n_in,
                              void* d_out, int out_size) {
    const float* x  = (const float*)d_in[0];
    const int*   ei = (const int*)d_in[1];
    const float* W1 = (const float*)d_in[2];
    const float* b1 = (const float*)d_in[3];
    const float* W2 = (const float*)d_in[4];
    const float* b2 = (const float*)d_in[5];
    const float* Wc = (const float*)d_in[6];
    const float* bc = (const float*)d_in[7];
    float* out = (float*)d_out;

    int N = in_sizes[0] / INC;
    int E = in_sizes[1] / 2;
    int nb = (N + SCAN_B - 1) / SCAN_B;

    // CSR build + dinv
    k_zero_deg<<<(N + 255) / 256, 256>>>(N);
    k_deg<<<(E + 255) / 256, 256>>>(ei, E);
    k_scan1<<<nb, SCAN_B>>>(N);
    k_scan2<<<1, 512>>>(nb);
    k_finalize<<<(N + 255) / 256, 256>>>(N);
    k_fill<<<(E + 255) / 256, 256>>>(ei, E);

    // Layer 1
    k_gemm1<<<(N + 127) / 128, 256>>>(x, W1, N);
    k_aggregate1<<<(N * 32 + 255) / 256, 256>>>(N);

    // Layer 2 (+ fused classifier)
    k_gemm2<<<(N + 127) / 128, 256>>>(W2, b1, N);
    k_agg_out<<<(N * 32 + 255) / 256, 256>>>(b2, Wc, bc, out, N);
}